// round 5
// baseline (speedup 1.0000x reference)
#include <cuda_runtime.h>

// out[b][j] = sum over pixels (y,x) of image b with (y & x) == j, j in [0,1024).
// bin j = ((y>>5)&(x>>5))<<5 | ((y&31)&(x&31)).
//
// Persistent work-stealing version: 740 CTAs (one full wave at 5 CTAs/SM),
// units of 8 rows x 1024 cols (8192 units), pulled from a global counter.
// Unit index u: b = u>>7, g = u&127 (8-row group), G = g>>2 (y hi-5 bits),
// glo = g&3 selects the compile-time row-template group.
// Runs of 4 consecutive u share (b, G) -> same output bins per lane, so lanes
// accumulate in registers across the run and flush (4 atomicAdds) only when
// the key u>>2 changes. Next unit index is prefetched (double-buffered smem)
// before processing the current unit, hiding the global-atomic latency.

#define FULLMASK 0xffffffffu
#define NUM_UNITS 8192u

__device__ unsigned int g_ctr;

__device__ __forceinline__ float shx(float v, int msk) {
    return __shfl_xor_sync(FULLMASK, v, msk);
}

template<int YLO>
__device__ __forceinline__ void proc_row(float4 v, int m,
                                         float& a0, float& a1, float& a2, float& a3) {
    constexpr int q  = YLO & 3;          // y bits 0,1
    constexpr int yh = (YLO >> 2) & 7;   // y bits 2,3,4
    float s0 = 0.f, s1 = 0.f, s2 = 0.f, s3 = 0.f;

    // Reduce x bits 0,1 in-register: s[p] = sum of v[e] with (e & q) == p.
    if constexpr (q == 0)      { s0 = (v.x + v.y) + (v.z + v.w); }
    else if constexpr (q == 1) { s0 = v.x + v.z;  s1 = v.y + v.w; }
    else if constexpr (q == 2) { s0 = v.x + v.y;  s2 = v.z + v.w; }
    else                       { s0 = v.x; s1 = v.y; s2 = v.z; s3 = v.w; }

    // Butterfly-reduce x bits 2..4 across lanes where the y bit is 0.
    if constexpr ((yh & 1) == 0) {
        s0 += shx(s0, 1);
        if constexpr (q & 1)  s1 += shx(s1, 1);
        if constexpr (q & 2)  s2 += shx(s2, 1);
        if constexpr (q == 3) s3 += shx(s3, 1);
    }
    if constexpr ((yh & 2) == 0) {
        s0 += shx(s0, 2);
        if constexpr (q & 1)  s1 += shx(s1, 2);
        if constexpr (q & 2)  s2 += shx(s2, 2);
        if constexpr (q == 3) s3 += shx(s3, 2);
    }
    if constexpr ((yh & 4) == 0) {
        s0 += shx(s0, 4);
        if constexpr (q & 1)  s1 += shx(s1, 4);
        if constexpr (q & 2)  s2 += shx(s2, 4);
        if constexpr (q == 3) s3 += shx(s3, 4);
    }

    // Lane m is the canonical owner iff m is a subset of yh.
    if ((m & ~yh & 7) == 0) {
        a0 += s0;
        if constexpr (q & 1)  a1 += s1;
        if constexpr (q & 2)  a2 += s2;
        if constexpr (q == 3) a3 += s3;
    }
}

template<int GLO>
__device__ __forceinline__ void do_group(const float* __restrict__ base, int lane, int m,
                                         float& a0, float& a1, float& a2, float& a3) {
    float4 vv[8];
    #pragma unroll
    for (int i = 0; i < 8; ++i)
        vv[i] = *reinterpret_cast<const float4*>(base + (size_t)i * 1024 + 4 * lane);
    proc_row<GLO*8+0>(vv[0], m, a0, a1, a2, a3);
    proc_row<GLO*8+1>(vv[1], m, a0, a1, a2, a3);
    proc_row<GLO*8+2>(vv[2], m, a0, a1, a2, a3);
    proc_row<GLO*8+3>(vv[3], m, a0, a1, a2, a3);
    proc_row<GLO*8+4>(vv[4], m, a0, a1, a2, a3);
    proc_row<GLO*8+5>(vv[5], m, a0, a1, a2, a3);
    proc_row<GLO*8+6>(vv[6], m, a0, a1, a2, a3);
    proc_row<GLO*8+7>(vv[7], m, a0, a1, a2, a3);
}

__global__ void __launch_bounds__(256, 5) CNNDST_bin_kernel(
        const float* __restrict__ M, float* __restrict__ out) {
    __shared__ unsigned int s_next[2];

    const int tid  = threadIdx.x;
    const int w    = tid >> 5;          // warp 0..7 -> cols [128w, 128w+128)
    const int lane = tid & 31;
    const int m    = lane & 7;
    const int t    = lane >> 3;         // column-tile (x>>5 low bits) within slice
    const int x5   = 4 * w + t;         // x>>5 for this lane's column-tile

    if (tid == 0) s_next[0] = atomicAdd(&g_ctr, 1u);
    __syncthreads();
    unsigned cur = s_next[0];
    int buf = 1;

    float a0 = 0.f, a1 = 0.f, a2 = 0.f, a3 = 0.f;

    while (cur < NUM_UNITS) {
        // Prefetch next unit index (hidden behind this unit's processing).
        if (tid == 0) s_next[buf] = atomicAdd(&g_ctr, 1u);

        const int b   = cur >> 7;       // image
        const int g   = cur & 127;      // 8-row group: rows [8g, 8g+8)
        const int glo = g & 3;          // low row bits -> template group

        const float* base = M + ((size_t)b << 20) + ((size_t)g << 13) + w * 128;
        switch (glo) {
            case 0: do_group<0>(base, lane, m, a0, a1, a2, a3); break;
            case 1: do_group<1>(base, lane, m, a0, a1, a2, a3); break;
            case 2: do_group<2>(base, lane, m, a0, a1, a2, a3); break;
            default: do_group<3>(base, lane, m, a0, a1, a2, a3); break;
        }

        __syncthreads();                // s_next[buf] now visible
        const unsigned nxt = s_next[buf];
        buf ^= 1;

        // Flush accumulators when the (b, G) key changes (incl. final unit:
        // nxt >= NUM_UNITS always differs in key since cur < NUM_UNITS).
        if ((nxt >> 2) != (cur >> 2)) {
            const int G  = (cur >> 2) & 31;   // y hi-5 bits
            const int hi = G & x5;            // high 5 bin bits
            float* o = out + ((size_t)b << 10) + (hi << 5) + (m << 2);
            atomicAdd(o + 0, a0);
            atomicAdd(o + 1, a1);
            atomicAdd(o + 2, a2);
            atomicAdd(o + 3, a3);
            a0 = a1 = a2 = a3 = 0.f;
        }
        cur = nxt;
    }
}

__global__ void CNNDST_zero_kernel(float* __restrict__ out) {
    out[(size_t)blockIdx.x * 1024 + threadIdx.x] = 0.f;
    if (blockIdx.x == 0 && threadIdx.x == 0) g_ctr = 0u;
}

extern "C" void kernel_launch(void* const* d_in, const int* in_sizes, int n_in,
                              void* d_out, int out_size) {
    const float* M = (const float*)d_in[0];   // (64, 1, 1024, 1024) float32
    float* out = (float*)d_out;               // (64, 1024) float32
    (void)in_sizes; (void)n_in; (void)out_size;

    CNNDST_zero_kernel<<<64, 1024>>>(out);
    CNNDST_bin_kernel<<<740, 256>>>(M, out);
}

// round 6
// speedup vs baseline: 1.8067x; 1.8067x over previous
#include <cuda_runtime.h>

// out[b][j] = sum over pixels (y,x) of image b with (y & x) == j, j in [0,1024).
// bin j = ((y>>5)&(x>>5))<<5 | ((y&31)&(x&31)).
//
// Per-WARP work stealing, NO barriers in the loop (R4's per-unit __syncthreads
// collapsed MLP and halved DRAM util — never again). Unit = 32 rows x 128 cols
// supertile, identical inner code to the proven static version: compile-time
// row templates, 8x LDG.128 batched per group, shfl_xor AND-reduction.
// Lane 0 steals the NEXT unit index at the top of the current unit (ATOMG
// latency hidden behind ~17us of unit work); shfl-broadcast at the end.
// 16384 units total; drain tail is warp-granular and BW-elastic.

#define FULLMASK 0xffffffffu
#define NUM_UNITS 16384u

__device__ unsigned int g_ctr;

__device__ __forceinline__ float shx(float v, int msk) {
    return __shfl_xor_sync(FULLMASK, v, msk);
}

template<int YLO>
__device__ __forceinline__ void proc_row(float4 v, int m,
                                         float& a0, float& a1, float& a2, float& a3) {
    constexpr int q  = YLO & 3;          // y bits 0,1
    constexpr int yh = (YLO >> 2) & 7;   // y bits 2,3,4
    float s0 = 0.f, s1 = 0.f, s2 = 0.f, s3 = 0.f;

    // Reduce x bits 0,1 in-register: s[p] = sum of v[e] with (e & q) == p.
    if constexpr (q == 0)      { s0 = (v.x + v.y) + (v.z + v.w); }
    else if constexpr (q == 1) { s0 = v.x + v.z;  s1 = v.y + v.w; }
    else if constexpr (q == 2) { s0 = v.x + v.y;  s2 = v.z + v.w; }
    else                       { s0 = v.x; s1 = v.y; s2 = v.z; s3 = v.w; }

    // Butterfly-reduce x bits 2..4 across lanes where the y bit is 0.
    if constexpr ((yh & 1) == 0) {
        s0 += shx(s0, 1);
        if constexpr (q & 1)  s1 += shx(s1, 1);
        if constexpr (q & 2)  s2 += shx(s2, 1);
        if constexpr (q == 3) s3 += shx(s3, 1);
    }
    if constexpr ((yh & 2) == 0) {
        s0 += shx(s0, 2);
        if constexpr (q & 1)  s1 += shx(s1, 2);
        if constexpr (q & 2)  s2 += shx(s2, 2);
        if constexpr (q == 3) s3 += shx(s3, 2);
    }
    if constexpr ((yh & 4) == 0) {
        s0 += shx(s0, 4);
        if constexpr (q & 1)  s1 += shx(s1, 4);
        if constexpr (q & 2)  s2 += shx(s2, 4);
        if constexpr (q == 3) s3 += shx(s3, 4);
    }

    // Lane m is the canonical owner iff m is a subset of yh.
    if ((m & ~yh & 7) == 0) {
        a0 += s0;
        if constexpr (q & 1)  a1 += s1;
        if constexpr (q & 2)  a2 += s2;
        if constexpr (q == 3) a3 += s3;
    }
}

template<int G>
__device__ __forceinline__ void do_group(const float* __restrict__ base, int lane, int m,
                                         float& a0, float& a1, float& a2, float& a3) {
    float4 vv[8];
    #pragma unroll
    for (int i = 0; i < 8; ++i)
        vv[i] = *reinterpret_cast<const float4*>(base + (size_t)(G * 8 + i) * 1024 + 4 * lane);
    proc_row<G*8+0>(vv[0], m, a0, a1, a2, a3);
    proc_row<G*8+1>(vv[1], m, a0, a1, a2, a3);
    proc_row<G*8+2>(vv[2], m, a0, a1, a2, a3);
    proc_row<G*8+3>(vv[3], m, a0, a1, a2, a3);
    proc_row<G*8+4>(vv[4], m, a0, a1, a2, a3);
    proc_row<G*8+5>(vv[5], m, a0, a1, a2, a3);
    proc_row<G*8+6>(vv[6], m, a0, a1, a2, a3);
    proc_row<G*8+7>(vv[7], m, a0, a1, a2, a3);
}

__global__ void __launch_bounds__(256, 5) CNNDST_bin_kernel(
        const float* __restrict__ M, float* __restrict__ out) {
    const int lane = threadIdx.x & 31;
    const int m    = lane & 7;
    const int t    = lane >> 3;           // column-tile within the 128-col slice

    unsigned cur = 0;
    if (lane == 0) cur = atomicAdd(&g_ctr, 1u);
    cur = __shfl_sync(FULLMASK, cur, 0);

    while (cur < NUM_UNITS) {
        // Steal the NEXT unit now; its latency hides behind this unit's work.
        unsigned nxt = 0;
        if (lane == 0) nxt = atomicAdd(&g_ctr, 1u);

        const int b  = cur >> 8;          // image
        const int r  = (cur >> 3) & 31;   // row-tile: rows [32r, 32r+32)
        const int wc = cur & 7;           // 128-col slice: cols [128wc, 128wc+128)

        const float* base = M + ((size_t)b << 20) + ((size_t)r << 15) + wc * 128;

        float a0 = 0.f, a1 = 0.f, a2 = 0.f, a3 = 0.f;
        do_group<0>(base, lane, m, a0, a1, a2, a3);
        do_group<1>(base, lane, m, a0, a1, a2, a3);
        do_group<2>(base, lane, m, a0, a1, a2, a3);
        do_group<3>(base, lane, m, a0, a1, a2, a3);

        const int hi = r & (4 * wc + t);  // high 5 bin bits
        float* o = out + ((size_t)b << 10) + (hi << 5) + (m << 2);
        atomicAdd(o + 0, a0);
        atomicAdd(o + 1, a1);
        atomicAdd(o + 2, a2);
        atomicAdd(o + 3, a3);

        cur = __shfl_sync(FULLMASK, nxt, 0);
    }
}

__global__ void CNNDST_zero_kernel(float* __restrict__ out) {
    out[(size_t)blockIdx.x * 1024 + threadIdx.x] = 0.f;
    if (blockIdx.x == 0 && threadIdx.x == 0) g_ctr = 0u;
}

extern "C" void kernel_launch(void* const* d_in, const int* in_sizes, int n_in,
                              void* d_out, int out_size) {
    const float* M = (const float*)d_in[0];   // (64, 1, 1024, 1024) float32
    float* out = (float*)d_out;               // (64, 1024) float32
    (void)in_sizes; (void)n_in; (void)out_size;

    CNNDST_zero_kernel<<<64, 1024>>>(out);
    CNNDST_bin_kernel<<<740, 256>>>(M, out);
}

// round 7
// speedup vs baseline: 1.9407x; 1.0741x over previous
#include <cuda_runtime.h>

// out[b][j] = sum over pixels (y,x) of image b with (y & x) == j, j in [0,1024).
// bin j = ((y>>5)&(x>>5))<<5 | ((y&31)&(x&31)).
//
// Static grid (proven best): 2048 CTAs = 64 images x 32 row-tiles, 8 warps per
// CTA each owning a 32-row x 128-col supertile. Fully unrolled 32-row body
// restructured as a rolling software pipeline with 8-row load lookahead:
// load row r+8 before processing row r, so each warp keeps ~8 LDG.128 in
// flight continuously instead of the burst-drain sawtooth ptxas produced at
// 46 regs. __launch_bounds__(256,4) raises the register cap to 64 so the
// lookahead buffer stays resident.

#define FULLMASK 0xffffffffu

__device__ __forceinline__ float shx(float v, int msk) {
    return __shfl_xor_sync(FULLMASK, v, msk);
}

template<int YLO>
__device__ __forceinline__ void proc_row(float4 v, int m,
                                         float& a0, float& a1, float& a2, float& a3) {
    constexpr int q  = YLO & 3;          // y bits 0,1
    constexpr int yh = (YLO >> 2) & 7;   // y bits 2,3,4
    float s0 = 0.f, s1 = 0.f, s2 = 0.f, s3 = 0.f;

    // Reduce x bits 0,1 in-register: s[p] = sum of v[e] with (e & q) == p.
    if constexpr (q == 0)      { s0 = (v.x + v.y) + (v.z + v.w); }
    else if constexpr (q == 1) { s0 = v.x + v.z;  s1 = v.y + v.w; }
    else if constexpr (q == 2) { s0 = v.x + v.y;  s2 = v.z + v.w; }
    else                       { s0 = v.x; s1 = v.y; s2 = v.z; s3 = v.w; }

    // Butterfly-reduce x bits 2..4 across lanes where the y bit is 0.
    if constexpr ((yh & 1) == 0) {
        s0 += shx(s0, 1);
        if constexpr (q & 1)  s1 += shx(s1, 1);
        if constexpr (q & 2)  s2 += shx(s2, 1);
        if constexpr (q == 3) s3 += shx(s3, 1);
    }
    if constexpr ((yh & 2) == 0) {
        s0 += shx(s0, 2);
        if constexpr (q & 1)  s1 += shx(s1, 2);
        if constexpr (q & 2)  s2 += shx(s2, 2);
        if constexpr (q == 3) s3 += shx(s3, 2);
    }
    if constexpr ((yh & 4) == 0) {
        s0 += shx(s0, 4);
        if constexpr (q & 1)  s1 += shx(s1, 4);
        if constexpr (q & 2)  s2 += shx(s2, 4);
        if constexpr (q == 3) s3 += shx(s3, 4);
    }

    // Lane m is the canonical owner iff m is a subset of yh.
    if ((m & ~yh & 7) == 0) {
        a0 += s0;
        if constexpr (q & 1)  a1 += s1;
        if constexpr (q & 2)  a2 += s2;
        if constexpr (q == 3) a3 += s3;
    }
}

__device__ __forceinline__ float4 ld_row(const float* __restrict__ base, int row, int lane) {
    return *reinterpret_cast<const float4*>(base + (size_t)row * 1024 + 4 * lane);
}

// Pipeline step: prefetch row ROW+8, process row ROW from the buffer, recurse.
template<int ROW>
__device__ __forceinline__ void step(const float* __restrict__ base, int lane, int m,
                                     float4 (&v)[8],
                                     float& a0, float& a1, float& a2, float& a3) {
    float4 nv;
    if constexpr (ROW + 8 < 32) nv = ld_row(base, ROW + 8, lane);
    proc_row<ROW>(v[ROW & 7], m, a0, a1, a2, a3);
    if constexpr (ROW + 8 < 32) v[ROW & 7] = nv;
    if constexpr (ROW + 1 < 32) step<ROW + 1>(base, lane, m, v, a0, a1, a2, a3);
}

__global__ void __launch_bounds__(256, 4) CNNDST_bin_kernel(
        const float* __restrict__ M, float* __restrict__ out) {
    const int blk  = blockIdx.x;       // 2048 blocks = 64 images * 32 row-tiles
    const int b    = blk >> 5;         // image
    const int r    = blk & 31;         // row-tile: rows [32r, 32r+32)
    const int w    = threadIdx.x >> 5; // warp 0..7 -> cols [128w, 128w+128)
    const int lane = threadIdx.x & 31;
    const int m    = lane & 7;

    const float* base = M + ((size_t)b << 20) + ((size_t)(r * 32)) * 1024 + w * 128;

    float4 v[8];
    #pragma unroll
    for (int i = 0; i < 8; ++i) v[i] = ld_row(base, i, lane);

    float a0 = 0.f, a1 = 0.f, a2 = 0.f, a3 = 0.f;
    step<0>(base, lane, m, v, a0, a1, a2, a3);

    const int t  = lane >> 3;           // column-tile within supertile
    const int hi = r & (4 * w + t);     // high 5 bin bits
    float* o = out + ((size_t)b << 10) + (hi << 5) + (m << 2);
    atomicAdd(o + 0, a0);
    atomicAdd(o + 1, a1);
    atomicAdd(o + 2, a2);
    atomicAdd(o + 3, a3);
}

__global__ void CNNDST_zero_kernel(float* __restrict__ out) {
    reinterpret_cast<float4*>(out)[blockIdx.x * 256 + threadIdx.x] =
        make_float4(0.f, 0.f, 0.f, 0.f);
}

extern "C" void kernel_launch(void* const* d_in, const int* in_sizes, int n_in,
                              void* d_out, int out_size) {
    const float* M = (const float*)d_in[0];   // (64, 1, 1024, 1024) float32
    float* out = (float*)d_out;               // (64, 1024) float32
    (void)in_sizes; (void)n_in; (void)out_size;

    CNNDST_zero_kernel<<<64, 256>>>(out);     // 65536 floats = 16384 float4
    CNNDST_bin_kernel<<<2048, 256>>>(M, out);
}